// round 1
// baseline (speedup 1.0000x reference)
#include <cuda_runtime.h>
#include <cuda_bf16.h>
#include <math.h>

// Problem constants
#define BB 4
#define SS 1024
#define DD 1024
#define HH 16
#define DQ 64
#define DV 32
#define BS (BB*SS)          // 4096 rows
#define HDQ (HH*DQ)         // 1024
#define HDV (HH*DV)         // 512

// Scratch (device globals — allocation-free rule)
__device__ float g_Q[BS * HDQ];                    // [4096,1024]
__device__ float g_K[BS * HDQ];                    // [4096,1024]
__device__ float g_V[BS * HDV];                    // [4096,512]
__device__ float g_S[(size_t)BB * HH * SS * SS];   // [64,1024,1024] scores
__device__ float g_ctx[BS * DD];                   // [4096,1024] concat(fwd,bwd) ctx

// ---------------------------------------------------------------------------
// Generic SGEMM: C[M,N] = A[M,K] @ B[K,N] + bias[N]
// 128x128 tile, BK=8, 8x8 microtile, 256 threads.
// ---------------------------------------------------------------------------
__global__ __launch_bounds__(256) void sgemm_bias_kernel(
    const float* __restrict__ A, const float* __restrict__ B,
    const float* __restrict__ bias, float* __restrict__ C,
    int M, int N, int K)
{
    __shared__ float As[8][132];
    __shared__ float Bs[8][132];

    const int m0 = blockIdx.y * 128;
    const int n0 = blockIdx.x * 128;
    const int tid = threadIdx.x;
    const int tr = tid >> 4;      // 0..15
    const int tc = tid & 15;      // 0..15

    const int arow = tid >> 1;          // 0..127
    const int ac4  = (tid & 1) * 4;     // 0 or 4
    const int brow = tid >> 5;          // 0..7
    const int bc4  = (tid & 31) * 4;    // 0..124

    float acc[8][8];
#pragma unroll
    for (int i = 0; i < 8; i++)
#pragma unroll
        for (int j = 0; j < 8; j++) acc[i][j] = 0.0f;

    for (int k0 = 0; k0 < K; k0 += 8) {
        float4 av = *(const float4*)(A + (size_t)(m0 + arow) * K + k0 + ac4);
        As[ac4 + 0][arow] = av.x;
        As[ac4 + 1][arow] = av.y;
        As[ac4 + 2][arow] = av.z;
        As[ac4 + 3][arow] = av.w;
        *(float4*)(&Bs[brow][bc4]) =
            *(const float4*)(B + (size_t)(k0 + brow) * N + n0 + bc4);
        __syncthreads();
#pragma unroll
        for (int kk = 0; kk < 8; kk++) {
            float4 a0 = *(const float4*)(&As[kk][tr * 8]);
            float4 a1 = *(const float4*)(&As[kk][tr * 8 + 4]);
            float4 b0 = *(const float4*)(&Bs[kk][tc * 8]);
            float4 b1 = *(const float4*)(&Bs[kk][tc * 8 + 4]);
            float ra[8] = {a0.x, a0.y, a0.z, a0.w, a1.x, a1.y, a1.z, a1.w};
            float rb[8] = {b0.x, b0.y, b0.z, b0.w, b1.x, b1.y, b1.z, b1.w};
#pragma unroll
            for (int i = 0; i < 8; i++)
#pragma unroll
                for (int j = 0; j < 8; j++) acc[i][j] += ra[i] * rb[j];
        }
        __syncthreads();
    }

#pragma unroll
    for (int i = 0; i < 8; i++) {
        int row = m0 + tr * 8 + i;
        int col = n0 + tc * 8;
        float4 bv0 = *(const float4*)(bias + col);
        float4 bv1 = *(const float4*)(bias + col + 4);
        float4 o0 = make_float4(acc[i][0] + bv0.x, acc[i][1] + bv0.y,
                                acc[i][2] + bv0.z, acc[i][3] + bv0.w);
        float4 o1 = make_float4(acc[i][4] + bv1.x, acc[i][5] + bv1.y,
                                acc[i][6] + bv1.z, acc[i][7] + bv1.w);
        *(float4*)(C + (size_t)row * N + col) = o0;
        *(float4*)(C + (size_t)row * N + col + 4) = o1;
    }
}

// ---------------------------------------------------------------------------
// Scores: per (b,h)  Sc = Q_h [S,64] @ K_h^T [64,S] * 0.125
// Both operands row-major [S, 64] slices with row stride 1024 (NT-GEMM).
// 128x128 tile, BK=16 (K=64 total), 8x8 microtile, 256 threads.
// ---------------------------------------------------------------------------
__global__ __launch_bounds__(256) void scores_kernel(float* __restrict__ Sc)
{
    const int bh = blockIdx.z;
    const int b = bh >> 4;
    const int h = bh & 15;
    const float* Ab = g_Q + (size_t)b * SS * HDQ + h * DQ;
    const float* Bb = g_K + (size_t)b * SS * HDQ + h * DQ;

    const int m0 = blockIdx.y * 128;
    const int n0 = blockIdx.x * 128;
    const int tid = threadIdx.x;
    const int tr = tid >> 4;
    const int tc = tid & 15;

    __shared__ float As[16][132];
    __shared__ float Bs[16][132];

    const int lrow = tid >> 2;         // 0..63
    const int lc4  = (tid & 3) * 4;    // 0,4,8,12

    float acc[8][8];
#pragma unroll
    for (int i = 0; i < 8; i++)
#pragma unroll
        for (int j = 0; j < 8; j++) acc[i][j] = 0.0f;

    for (int k0 = 0; k0 < DQ; k0 += 16) {
#pragma unroll
        for (int p = 0; p < 2; p++) {
            int r = lrow + p * 64;
            float4 av = *(const float4*)(Ab + (size_t)(m0 + r) * HDQ + k0 + lc4);
            As[lc4 + 0][r] = av.x;
            As[lc4 + 1][r] = av.y;
            As[lc4 + 2][r] = av.z;
            As[lc4 + 3][r] = av.w;
            float4 bv = *(const float4*)(Bb + (size_t)(n0 + r) * HDQ + k0 + lc4);
            Bs[lc4 + 0][r] = bv.x;
            Bs[lc4 + 1][r] = bv.y;
            Bs[lc4 + 2][r] = bv.z;
            Bs[lc4 + 3][r] = bv.w;
        }
        __syncthreads();
#pragma unroll
        for (int kk = 0; kk < 16; kk++) {
            float4 a0 = *(const float4*)(&As[kk][tr * 8]);
            float4 a1 = *(const float4*)(&As[kk][tr * 8 + 4]);
            float4 b0 = *(const float4*)(&Bs[kk][tc * 8]);
            float4 b1 = *(const float4*)(&Bs[kk][tc * 8 + 4]);
            float ra[8] = {a0.x, a0.y, a0.z, a0.w, a1.x, a1.y, a1.z, a1.w};
            float rb[8] = {b0.x, b0.y, b0.z, b0.w, b1.x, b1.y, b1.z, b1.w};
#pragma unroll
            for (int i = 0; i < 8; i++)
#pragma unroll
                for (int j = 0; j < 8; j++) acc[i][j] += ra[i] * rb[j];
        }
        __syncthreads();
    }

    float* Cb = Sc + (size_t)bh * SS * SS;
#pragma unroll
    for (int i = 0; i < 8; i++) {
        int row = m0 + tr * 8 + i;
        int col = n0 + tc * 8;
        float4 o0 = make_float4(acc[i][0] * 0.125f, acc[i][1] * 0.125f,
                                acc[i][2] * 0.125f, acc[i][3] * 0.125f);
        float4 o1 = make_float4(acc[i][4] * 0.125f, acc[i][5] * 0.125f,
                                acc[i][6] * 0.125f, acc[i][7] * 0.125f);
        *(float4*)(Cb + (size_t)row * SS + col) = o0;
        *(float4*)(Cb + (size_t)row * SS + col + 4) = o1;
    }
}

// ---------------------------------------------------------------------------
// Softmax: per (bh, 32-row q-tile): fwd softmax over keys<=q, bwd over keys>=q.
// Writes both prob matrices to attn region of d_out.
// 256 threads, dyn smem = 32 * 1032 floats (stride 1032 -> bank-conflict-free
// column scans since 8*r + t covers all 32 banks).
// ---------------------------------------------------------------------------
#define SMROW 1032
__global__ __launch_bounds__(256) void softmax_kernel(
    const float* __restrict__ Sc, float* __restrict__ attn)
{
    extern __shared__ float ssc[];
    __shared__ float mF[32], iF[32], mB[32], iB[32];

    const int bh = blockIdx.y;
    const int q0 = blockIdx.x * 32;
    const int tid = threadIdx.x;

    const float* src = Sc + (size_t)bh * SS * SS + (size_t)q0 * SS;
    for (int i = tid; i < 32 * SS; i += 256) {
        int r = i >> 10, k = i & 1023;
        ssc[r * SMROW + k] = src[i];
    }
    __syncthreads();

    const int r = tid >> 3;     // 0..31 (row)
    const int t = tid & 7;      // 0..7
    const int q = q0 + r;
    const float* row = ssc + r * SMROW;

    float mf = -1e30f, mb = -1e30f;
#pragma unroll 8
    for (int i = 0; i < 128; i++) {
        int k = t + (i << 3);
        float v = row[k];
        if (k <= q) mf = fmaxf(mf, v);
        if (k >= q) mb = fmaxf(mb, v);
    }
#pragma unroll
    for (int o = 4; o > 0; o >>= 1) {
        mf = fmaxf(mf, __shfl_xor_sync(0xffffffffu, mf, o));
        mb = fmaxf(mb, __shfl_xor_sync(0xffffffffu, mb, o));
    }
    float sf = 0.0f, sb = 0.0f;
#pragma unroll 8
    for (int i = 0; i < 128; i++) {
        int k = t + (i << 3);
        float v = row[k];
        if (k <= q) sf += __expf(v - mf);
        if (k >= q) sb += __expf(v - mb);
    }
#pragma unroll
    for (int o = 4; o > 0; o >>= 1) {
        sf += __shfl_xor_sync(0xffffffffu, sf, o);
        sb += __shfl_xor_sync(0xffffffffu, sb, o);
    }
    if (t == 0) {
        mF[r] = mf; iF[r] = 1.0f / sf;
        mB[r] = mb; iB[r] = 1.0f / sb;
    }
    __syncthreads();

    float* dst = attn + (size_t)bh * SS * 2 * SS + (size_t)q0 * 2 * SS;
    for (int i = tid; i < 32 * SS; i += 256) {
        int rr = i >> 10, k = i & 1023;
        int qq = q0 + rr;
        float v = ssc[rr * SMROW + k];
        float pf = (k <= qq) ? __expf(v - mF[rr]) * iF[rr] : 0.0f;
        float pb = (k >= qq) ? __expf(v - mB[rr]) * iB[rr] : 0.0f;
        dst[(size_t)rr * 2048 + k] = pf;
        dst[(size_t)rr * 2048 + 1024 + k] = pb;
    }
}

// ---------------------------------------------------------------------------
// PV: per (bh, dir, 128-row q-tile): ctx_tile[128,32] = P[128,1024] @ V[1024,32]
// P read from d_out attn region. 128 threads, BK=16, 8x4 microtile.
// Writes into g_ctx at column dir*512 + h*32.
// ---------------------------------------------------------------------------
__global__ __launch_bounds__(128) void pv_kernel(const float* __restrict__ attn)
{
    const int bh = blockIdx.z;
    const int dir = blockIdx.y;
    const int q0 = blockIdx.x * 128;
    const int b = bh >> 4;
    const int h = bh & 15;

    const float* Pb = attn + (size_t)bh * SS * 2 * SS + dir * SS; // P[q][k] at +q*2048+k
    const float* Vb = g_V + (size_t)b * SS * HDV + h * DV;        // V[k][d] at +k*512+d

    __shared__ float Ps[16][132];
    __shared__ float Vs[16][32];

    const int tid = threadIdx.x;
    const int tr = tid >> 3;   // 0..15
    const int tc = tid & 7;    // 0..7

    float acc[8][4];
#pragma unroll
    for (int i = 0; i < 8; i++)
#pragma unroll
        for (int j = 0; j < 4; j++) acc[i][j] = 0.0f;

    const int prow = tid >> 2;        // 0..31
    const int pc4  = (tid & 3) * 4;   // 0,4,8,12
    const int vk   = tid >> 3;        // 0..15
    const int vd4  = (tid & 7) * 4;   // 0..28

    for (int k0 = 0; k0 < SS; k0 += 16) {
#pragma unroll
        for (int p = 0; p < 4; p++) {
            int qr = prow + p * 32;
            float4 pv = *(const float4*)(Pb + (size_t)(q0 + qr) * 2048 + k0 + pc4);
            Ps[pc4 + 0][qr] = pv.x;
            Ps[pc4 + 1][qr] = pv.y;
            Ps[pc4 + 2][qr] = pv.z;
            Ps[pc4 + 3][qr] = pv.w;
        }
        *(float4*)(&Vs[vk][vd4]) =
            *(const float4*)(Vb + (size_t)(k0 + vk) * HDV + vd4);
        __syncthreads();
#pragma unroll
        for (int kk = 0; kk < 16; kk++) {
            float4 a0 = *(const float4*)(&Ps[kk][tr * 8]);
            float4 a1 = *(const float4*)(&Ps[kk][tr * 8 + 4]);
            float4 bb = *(const float4*)(&Vs[kk][tc * 4]);
            float ra[8] = {a0.x, a0.y, a0.z, a0.w, a1.x, a1.y, a1.z, a1.w};
            float rb[4] = {bb.x, bb.y, bb.z, bb.w};
#pragma unroll
            for (int i = 0; i < 8; i++)
#pragma unroll
                for (int j = 0; j < 4; j++) acc[i][j] += ra[i] * rb[j];
        }
        __syncthreads();
    }

    const int colbase = dir * HDV + h * DV + tc * 4;
#pragma unroll
    for (int i = 0; i < 8; i++) {
        int qr = q0 + tr * 8 + i;
        float4 o = make_float4(acc[i][0], acc[i][1], acc[i][2], acc[i][3]);
        *(float4*)(g_ctx + (size_t)((size_t)b * SS + qr) * DD + colbase) = o;
    }
}

// ---------------------------------------------------------------------------
// Launch
// ---------------------------------------------------------------------------
extern "C" void kernel_launch(void* const* d_in, const int* in_sizes, int n_in,
                              void* d_out, int out_size)
{
    const float* x  = (const float*)d_in[0];
    const float* Wq = (const float*)d_in[1];
    const float* bq = (const float*)d_in[2];
    const float* Wk = (const float*)d_in[3];
    const float* bk = (const float*)d_in[4];
    const float* Wv = (const float*)d_in[5];
    const float* bv = (const float*)d_in[6];
    const float* Wo = (const float*)d_in[7];
    const float* bo = (const float*)d_in[8];

    float* out  = (float*)d_out;                       // [B,S,D]
    float* attn = out + (size_t)BS * DD;               // [B,H,S,2S]

    float *pQ, *pK, *pV, *pS, *pC;
    cudaGetSymbolAddress((void**)&pQ, g_Q);
    cudaGetSymbolAddress((void**)&pK, g_K);
    cudaGetSymbolAddress((void**)&pV, g_V);
    cudaGetSymbolAddress((void**)&pS, g_S);
    cudaGetSymbolAddress((void**)&pC, g_ctx);

    // QKV projections
    sgemm_bias_kernel<<<dim3(HDQ / 128, BS / 128), 256>>>(x, Wq, bq, pQ, BS, HDQ, DD);
    sgemm_bias_kernel<<<dim3(HDQ / 128, BS / 128), 256>>>(x, Wk, bk, pK, BS, HDQ, DD);
    sgemm_bias_kernel<<<dim3(HDV / 128, BS / 128), 256>>>(x, Wv, bv, pV, BS, HDV, DD);

    // Scores
    scores_kernel<<<dim3(SS / 128, SS / 128, BB * HH), 256>>>(pS);

    // Softmax + prob write (both directions)
    static const int smbytes = 32 * SMROW * 4;
    cudaFuncSetAttribute(softmax_kernel,
                         cudaFuncAttributeMaxDynamicSharedMemorySize, smbytes);
    softmax_kernel<<<dim3(SS / 32, BB * HH), 256, smbytes>>>(pS, attn);

    // PV
    pv_kernel<<<dim3(SS / 128, 2, BB * HH), 128>>>(attn);

    // Output projection
    sgemm_bias_kernel<<<dim3(DD / 128, BS / 128), 256>>>(pC, Wo, bo, out, BS, DD, DD);
}